// round 8
// baseline (speedup 1.0000x reference)
#include <cuda_runtime.h>
#include <cuda_fp16.h>
#include <math.h>

#define BATCH 4
#define CH    128
#define HH    384
#define WW    384
#define HW    (HH*WW)          // 147456
#define NPIX  (BATCH*HW)

#define MAXSEL_B ((HH-4)*(WW-4))          // 144400 per batch
#define CTXB ((MAXSEL_B + 63) / 64)       // 2257 blocks per batch launch
#define DONE_TOTAL (BATCH * CTXB)

// Scratch (allocation-free: __device__ globals)
__device__ __half        g_Th[(size_t)NPIX * CH]; // [B,H,W,C] fp16 features
__device__ float         g_inv[NPIX];
__device__ unsigned char g_cls[NPIX];
__device__ int           g_list[NPIX];            // per-batch segments at b*HW
__device__ float         g_acc[BATCH];
__device__ int           g_cnt[BATCH];            // compaction base AND final count
__device__ int           g_bnd[BATCH];
__device__ int           g_done;

__constant__ int c_off[24] = {
    -770,-769,-768,-767,-766,
    -386,-385,-384,-383,-382,
      -2,  -1,   1,   2,
     382, 383, 384, 385, 386,
     766, 767, 768, 769, 770 };

// ---------------------------------------------------------------------------
__global__ void zero_kernel() {
    if (threadIdx.x == 0) g_done = 0;
    if (threadIdx.x < BATCH) {
        g_acc[threadIdx.x] = 0.0f;
        g_cnt[threadIdx.x] = 0;
        g_bnd[threadIdx.x] = 0;
    }
}

// ---------------------------------------------------------------------------
// 1. per-batch transpose [C,H,W] -> [H,W,C] fp16 + inv-norm + prep/compaction
__global__ void transpose_kernel(const float* __restrict__ er,
                                 const int* __restrict__ seg,
                                 const int* __restrict__ gtb, int b) {
    __shared__ float tile[32][33];
    __shared__ float red[8][32];
    int tx = threadIdx.x, ty = threadIdx.y;
    int t  = ty * 32 + tx;
    int p0 = blockIdx.x * 32;
    int px = t >> 3;
    int j  = t & 7;

    __half2* outp = (__half2*)g_Th + ((size_t)(b * HW) + p0) * (CH / 2);

    float sq = 0.0f;
    for (int c0 = 0; c0 < CH; c0 += 32) {
        if (c0) __syncthreads();
#pragma unroll
        for (int i = 0; i < 4; i++) {
            int c = c0 + ty + 8 * i;
            float v = er[((size_t)(b * CH + c)) * HW + p0 + tx];
            tile[ty + 8 * i][tx] = v;
            sq += v * v;
        }
        __syncthreads();
#pragma unroll
        for (int k = 0; k < 2; k++) {
            int jj = j + 8 * k;
            __half2 h = __floats2half2_rn(tile[2 * jj][px], tile[2 * jj + 1][px]);
            outp[(size_t)px * (CH / 2) + c0 / 2 + jj] = h;
        }
    }
    red[ty][tx] = sq;
    __syncthreads();
    if (ty == 0) {
        float s = 0.0f;
#pragma unroll
        for (int k = 0; k < 8; k++) s += red[k][tx];
        int rem = p0 + tx;
        int p   = b * HW + rem;
        g_inv[p] = 1.0f / fmaxf(sqrtf(s), 1e-8f);

        int y = rem / WW;
        int x = rem - y * WW;
        int s1r = seg[((size_t)(b * 2 + 1)) * HW + rem];
        int gt  = gtb[p];            if (gt == 255) gt = 0;
        int s1  = s1r;               if (s1 == 255) s1 = 0;
        bool bnd = (gt * s1) > 0;
        bool inter = (y >= 2) && (y <= HH - 3) && (x >= 2) && (x <= WW - 3);
        bool sel = bnd && inter;
        g_cls[p] = (unsigned char)s1r;

        unsigned selm = __ballot_sync(0xffffffffu, sel);
        unsigned bndm = __ballot_sync(0xffffffffu, bnd);
        int base = 0;
        if (tx == 0 && selm) base = atomicAdd(&g_cnt[b], __popc(selm));
        if (tx == 0 && bndm) atomicOr(&g_bnd[b], 1);
        base = __shfl_sync(0xffffffffu, base, 0);
        if (sel) g_list[b * HW + base + __popc(selm & ((1u << tx) - 1u))] = p;
    }
}

// ---------------------------------------------------------------------------
// 2. per-batch ctx: 8 pixels/warp, 4 lanes/pixel; 3 neighbor groups; fused fin
__global__ void __launch_bounds__(256, 5)
ctx_kernel(float* __restrict__ out, int b) {
    __shared__ float s_acc;
    int tid  = threadIdx.x;
    int nsel = g_cnt[b];

    if (blockIdx.x * 64 < nsel) {
        if (tid == 0) s_acc = 0.0f;
        __syncthreads();

        int warp = blockIdx.x * 8 + (tid >> 5);
        int lane = tid & 31;
        int grp  = lane >> 2;
        int sub  = lane & 3;

        int idx = warp * 8 + grp;
        bool active = idx < nsel;
        int p = active ? g_list[b * HW + idx] : (b * HW + 2 * WW + 2);

        const uint4* base4 = (const uint4*)(g_Th + (size_t)p * CH);
        __half2 chv[16];
#pragma unroll
        for (int k = 0; k < 4; k++)
            *(uint4*)&chv[4 * k] = base4[sub + 4 * k];
        float invc = g_inv[p];
        unsigned char cp = g_cls[p];

        float acc = 0.0f;
#pragma unroll
        for (int g = 0; g < 3; g++) {
            float dots[8];
#pragma unroll
            for (int jj = 0; jj < 8; jj++) {
                int q = p + c_off[g * 8 + jj];
                const uint4* nb4 = (const uint4*)(g_Th + (size_t)q * CH);
                uint4 n0 = nb4[sub], n1 = nb4[sub + 4], n2 = nb4[sub + 8], n3 = nb4[sub + 12];
                const __half2* h0 = (const __half2*)&n0;
                const __half2* h1 = (const __half2*)&n1;
                const __half2* h2 = (const __half2*)&n2;
                const __half2* h3 = (const __half2*)&n3;
                __half2 d = __hmul2(chv[0], h0[0]);
                d = __hfma2(chv[1],  h0[1], d);
                d = __hfma2(chv[2],  h0[2], d);
                d = __hfma2(chv[3],  h0[3], d);
                d = __hfma2(chv[4],  h1[0], d);
                d = __hfma2(chv[5],  h1[1], d);
                d = __hfma2(chv[6],  h1[2], d);
                d = __hfma2(chv[7],  h1[3], d);
                d = __hfma2(chv[8],  h2[0], d);
                d = __hfma2(chv[9],  h2[1], d);
                d = __hfma2(chv[10], h2[2], d);
                d = __hfma2(chv[11], h2[3], d);
                d = __hfma2(chv[12], h3[0], d);
                d = __hfma2(chv[13], h3[1], d);
                d = __hfma2(chv[14], h3[2], d);
                d = __hfma2(chv[15], h3[3], d);
                float2 f2 = __half22float2(d);
                dots[jj] = f2.x + f2.y;
            }
#pragma unroll
            for (int m = 1; m <= 2; m <<= 1) {
#pragma unroll
                for (int jj = 0; jj < 8; jj++)
                    dots[jj] += __shfl_xor_sync(0xffffffffu, dots[jj], m);
            }
            if (active) {
#pragma unroll
                for (int tt = 0; tt < 2; tt++) {
                    int jj = sub + 4 * tt;
                    int q = p + c_off[g * 8 + jj];
                    float cosv = dots[jj] * invc * g_inv[q];
                    float lab  = (g_cls[q] == cp) ? 1.0f : 0.0f;
                    float e = cosv - lab;
                    acc += e * e;
                }
            }
        }
#pragma unroll
        for (int m = 1; m <= 2; m <<= 1)
            acc += __shfl_xor_sync(0xffffffffu, acc, m);
        if (sub == 0 && active) atomicAdd(&s_acc, acc);

        __syncthreads();
        if (tid == 0 && s_acc != 0.0f) atomicAdd(&g_acc[b], s_acc);
    }

    // fused finalize: last ctx block chip-wide computes the scalar output
    if (tid == 0) {
        __threadfence();
        int done = atomicAdd(&g_done, 1);
        if (done == DONE_TOTAL - 1) {
            float tot = 0.0f, nv = 0.0f;
            for (int bb = 0; bb < BATCH; bb++) {
                float lb = g_acc[bb] / fmaxf((float)g_cnt[bb], 1.0f) / 24.0f;
                if (g_bnd[bb]) { tot += lb; nv += 1.0f; }
            }
            tot = tot / fmaxf(nv, 1.0f);
            if (isnan(tot)) tot = 0.0f;
            out[0] = tot;
        }
    }
}

// ---------------------------------------------------------------------------
extern "C" void kernel_launch(void* const* d_in, const int* in_sizes, int n_in,
                              void* d_out, int out_size) {
    const float* er  = (const float*)d_in[0];
    const int*   seg = (const int*)d_in[1];
    const int*   gtb = (const int*)d_in[2];
    float*       out = (float*)d_out;

    static cudaStream_t s1 = nullptr;
    static cudaEvent_t  ev[BATCH], evj;
    if (!s1) {
        cudaStreamCreateWithFlags(&s1, cudaStreamNonBlocking);
        for (int i = 0; i < BATCH; i++)
            cudaEventCreateWithFlags(&ev[i], cudaEventDisableTiming);
        cudaEventCreateWithFlags(&evj, cudaEventDisableTiming);
    }

    zero_kernel<<<1, 32>>>();
    for (int b = 0; b < BATCH; b++) {
        transpose_kernel<<<HW / 32, dim3(32, 8)>>>(er, seg, gtb, b);
        cudaEventRecord(ev[b], 0);
        cudaStreamWaitEvent(s1, ev[b], 0);
        ctx_kernel<<<CTXB, 256, 0, s1>>>(out, b);
    }
    cudaEventRecord(evj, s1);
    cudaStreamWaitEvent(0, evj, 0);
}

// round 9
// speedup vs baseline: 1.1339x; 1.1339x over previous
#include <cuda_runtime.h>
#include <cuda_fp16.h>
#include <math.h>

#define BATCH 4
#define CH    128
#define HH    384
#define WW    384
#define HW    (HH*WW)          // 147456
#define NPIX  (BATCH*HW)

#define MAXSEL ((HH-4)*(WW-4)*BATCH)      // 577600
#define CTX_BLOCKS ((MAXSEL + 63) / 64)   // 8 warps/block, 8 px/warp

// Scratch (allocation-free: __device__ globals)
__device__ __half        g_Th[(size_t)NPIX * CH]; // [B,H,W,C] fp16 features
__device__ float         g_inv[NPIX];
__device__ unsigned char g_cls[NPIX];
__device__ int           g_list[NPIX];
__device__ int           g_nsel;
__device__ float         g_acc[BATCH];
__device__ int           g_cnt[BATCH];
__device__ int           g_bnd[BATCH];
__device__ int           g_done;

__constant__ int c_off[24] = {
    -770,-769,-768,-767,-766,
    -386,-385,-384,-383,-382,
      -2,  -1,   1,   2,
     382, 383, 384, 385, 386,
     766, 767, 768, 769, 770 };

// ---------------------------------------------------------------------------
__global__ void zero_kernel() {
    if (threadIdx.x == 0) { g_nsel = 0; g_done = 0; }
    if (threadIdx.x < BATCH) {
        g_acc[threadIdx.x] = 0.0f;
        g_cnt[threadIdx.x] = 0;
        g_bnd[threadIdx.x] = 0;
    }
}

// ---------------------------------------------------------------------------
// 1. transpose [B,C,H,W] -> [B,H,W,C] fp16 with STG.128 stores,
//    fused fp32 inv-norm + prep (mask/compaction/class).
//    Block: 32 pixels x 128 channels, 2 chunks of 64 channels.
__global__ void transpose_kernel(const float* __restrict__ er,
                                 const int* __restrict__ seg,
                                 const int* __restrict__ gtb) {
    __shared__ float tile[64][33];
    __shared__ float red[8][32];
    int tx = threadIdx.x, ty = threadIdx.y;
    int t  = ty * 32 + tx;
    int p0 = blockIdx.x * 32;
    int b  = blockIdx.y;
    int px   = t >> 3;                // output pixel 0..31
    int quad = t & 7;                 // uint4 index within 64-ch chunk

    uint4* out4 = (uint4*)g_Th + ((size_t)(b * HW) + p0) * 16;

    float sq = 0.0f;
#pragma unroll
    for (int c0 = 0; c0 < CH; c0 += 64) {
        if (c0) __syncthreads();
#pragma unroll
        for (int i = 0; i < 8; i++) {
            int c = c0 + ty + 8 * i;
            float v = er[((size_t)(b * CH + c)) * HW + p0 + tx];  // 128B coalesced
            tile[ty + 8 * i][tx] = v;
            sq += v * v;
        }
        __syncthreads();
        // each thread: 8 floats -> 4 half2 -> one STG.128
        __half2 h[4];
#pragma unroll
        for (int m = 0; m < 4; m++)
            h[m] = __floats2half2_rn(tile[8 * quad + 2 * m][px],
                                     tile[8 * quad + 2 * m + 1][px]);
        out4[(size_t)px * 16 + c0 / 8 + quad] = *(uint4*)h;
    }
    red[ty][tx] = sq;
    __syncthreads();
    if (ty == 0) {   // warp 0: inv-norm + prep for this block's 32 pixels
        float s = 0.0f;
#pragma unroll
        for (int k = 0; k < 8; k++) s += red[k][tx];
        int rem = p0 + tx;
        int p   = b * HW + rem;
        g_inv[p] = 1.0f / fmaxf(sqrtf(s), 1e-8f);

        int y = rem / WW;
        int x = rem - y * WW;
        int s1r = seg[((size_t)(b * 2 + 1)) * HW + rem];
        int gt  = gtb[p];            if (gt == 255) gt = 0;
        int s1  = s1r;               if (s1 == 255) s1 = 0;
        bool bnd = (gt * s1) > 0;
        bool inter = (y >= 2) && (y <= HH - 3) && (x >= 2) && (x <= WW - 3);
        bool sel = bnd && inter;
        g_cls[p] = (unsigned char)s1r;

        unsigned selm = __ballot_sync(0xffffffffu, sel);
        unsigned bndm = __ballot_sync(0xffffffffu, bnd);
        int base = 0;
        if (tx == 0 && selm) {
            base = atomicAdd(&g_nsel, __popc(selm));
            atomicAdd(&g_cnt[b], __popc(selm));
        }
        if (tx == 0 && bndm) atomicOr(&g_bnd[b], 1);
        base = __shfl_sync(0xffffffffu, base, 0);
        if (sel) g_list[base + __popc(selm & ((1u << tx) - 1u))] = p;
    }
}

// ---------------------------------------------------------------------------
// 2. main: 8 pixels/warp, 4 lanes/pixel (32 ch/lane); 3 neighbor groups;
//    packed HFMA2; fused finalize
__global__ void __launch_bounds__(256, 5)
ctx_kernel(float* __restrict__ out) {
    __shared__ float sacc[BATCH];
    int tid  = threadIdx.x;
    int nsel = g_nsel;

    if (blockIdx.x * 64 < nsel) {
        if (tid < BATCH) sacc[tid] = 0.0f;
        __syncthreads();

        int warp = blockIdx.x * 8 + (tid >> 5);
        int lane = tid & 31;
        int grp  = lane >> 2;
        int sub  = lane & 3;

        int idx = warp * 8 + grp;
        bool active = idx < nsel;
        int p = active ? g_list[idx] : (2 * WW + 2);

        const uint4* base4 = (const uint4*)(g_Th + (size_t)p * CH);
        __half2 chv[16];
#pragma unroll
        for (int k = 0; k < 4; k++)
            *(uint4*)&chv[4 * k] = base4[sub + 4 * k];
        float invc = g_inv[p];
        unsigned char cp = g_cls[p];

        float acc = 0.0f;
#pragma unroll
        for (int g = 0; g < 3; g++) {
            float dots[8];
#pragma unroll
            for (int jj = 0; jj < 8; jj++) {
                int q = p + c_off[g * 8 + jj];
                const uint4* nb4 = (const uint4*)(g_Th + (size_t)q * CH);
                uint4 n0 = nb4[sub], n1 = nb4[sub + 4], n2 = nb4[sub + 8], n3 = nb4[sub + 12];
                const __half2* h0 = (const __half2*)&n0;
                const __half2* h1 = (const __half2*)&n1;
                const __half2* h2 = (const __half2*)&n2;
                const __half2* h3 = (const __half2*)&n3;
                __half2 d = __hmul2(chv[0], h0[0]);
                d = __hfma2(chv[1],  h0[1], d);
                d = __hfma2(chv[2],  h0[2], d);
                d = __hfma2(chv[3],  h0[3], d);
                d = __hfma2(chv[4],  h1[0], d);
                d = __hfma2(chv[5],  h1[1], d);
                d = __hfma2(chv[6],  h1[2], d);
                d = __hfma2(chv[7],  h1[3], d);
                d = __hfma2(chv[8],  h2[0], d);
                d = __hfma2(chv[9],  h2[1], d);
                d = __hfma2(chv[10], h2[2], d);
                d = __hfma2(chv[11], h2[3], d);
                d = __hfma2(chv[12], h3[0], d);
                d = __hfma2(chv[13], h3[1], d);
                d = __hfma2(chv[14], h3[2], d);
                d = __hfma2(chv[15], h3[3], d);
                float2 f2 = __half22float2(d);
                dots[jj] = f2.x + f2.y;
            }
#pragma unroll
            for (int m = 1; m <= 2; m <<= 1) {
#pragma unroll
                for (int jj = 0; jj < 8; jj++)
                    dots[jj] += __shfl_xor_sync(0xffffffffu, dots[jj], m);
            }
            if (active) {
#pragma unroll
                for (int tt = 0; tt < 2; tt++) {
                    int jj = sub + 4 * tt;
                    int q = p + c_off[g * 8 + jj];
                    float cosv = dots[jj] * invc * g_inv[q];
                    float lab  = (g_cls[q] == cp) ? 1.0f : 0.0f;
                    float e = cosv - lab;
                    acc += e * e;
                }
            }
        }
#pragma unroll
        for (int m = 1; m <= 2; m <<= 1)
            acc += __shfl_xor_sync(0xffffffffu, acc, m);
        if (sub == 0 && active) atomicAdd(&sacc[p / HW], acc);

        __syncthreads();
        if (tid < BATCH) {
            float v = sacc[tid];
            if (v != 0.0f) atomicAdd(&g_acc[tid], v);
        }
        __syncthreads();
    }

    // fused finalize
    if (tid == 0) {
        __threadfence();
        int done = atomicAdd(&g_done, 1);
        if (done == (int)gridDim.x - 1) {
            float tot = 0.0f, nv = 0.0f;
            for (int b = 0; b < BATCH; b++) {
                float lb = g_acc[b] / fmaxf((float)g_cnt[b], 1.0f) / 24.0f;
                if (g_bnd[b]) { tot += lb; nv += 1.0f; }
            }
            tot = tot / fmaxf(nv, 1.0f);
            if (isnan(tot)) tot = 0.0f;
            out[0] = tot;
        }
    }
}

// ---------------------------------------------------------------------------
extern "C" void kernel_launch(void* const* d_in, const int* in_sizes, int n_in,
                              void* d_out, int out_size) {
    const float* er  = (const float*)d_in[0];
    const int*   seg = (const int*)d_in[1];
    const int*   gtb = (const int*)d_in[2];
    float*       out = (float*)d_out;

    zero_kernel<<<1, 32>>>();
    transpose_kernel<<<dim3(HW / 32, BATCH), dim3(32, 8)>>>(er, seg, gtb);
    ctx_kernel<<<CTX_BLOCKS, 256>>>(out);
}

// round 10
// speedup vs baseline: 1.1681x; 1.0301x over previous
#include <cuda_runtime.h>
#include <cuda_fp16.h>
#include <math.h>

#define BATCH 4
#define CH    128
#define HH    384
#define WW    384
#define HW    (HH*WW)          // 147456
#define NPIX  (BATCH*HW)

#define MAXSEL ((HH-4)*(WW-4)*BATCH)      // 577600
#define CTX_BLOCKS ((MAXSEL + 31) / 32)   // 8 warps/block, 4 px/warp

// Scratch (allocation-free: __device__ globals; zero-initialized at load,
// re-zeroed by the finalize block at the end of every run)
__device__ __half        g_Th[(size_t)NPIX * CH]; // [B,H,W,C] fp16 features
__device__ float         g_inv[NPIX];
__device__ unsigned char g_cls[NPIX];
__device__ int           g_list[NPIX];
__device__ int           g_nsel;
__device__ float         g_acc[BATCH];
__device__ int           g_cnt[BATCH];
__device__ int           g_bnd[BATCH];
__device__ int           g_done;

__constant__ int c_off[24] = {
    -770,-769,-768,-767,-766,
    -386,-385,-384,-383,-382,
      -2,  -1,   1,   2,
     382, 383, 384, 385, 386,
     766, 767, 768, 769, 770 };

// ---------------------------------------------------------------------------
// 1. transpose [B,C,H,W] -> [B,H,W,C] fp16 with STG.128 stores,
//    fused fp32 inv-norm + prep (mask/compaction/class).
__global__ void transpose_kernel(const float* __restrict__ er,
                                 const int* __restrict__ seg,
                                 const int* __restrict__ gtb) {
    __shared__ float tile[64][33];
    __shared__ float red[8][32];
    int tx = threadIdx.x, ty = threadIdx.y;
    int t  = ty * 32 + tx;
    int p0 = blockIdx.x * 32;
    int b  = blockIdx.y;
    int px   = t >> 3;                // output pixel 0..31
    int quad = t & 7;                 // uint4 index within 64-ch chunk

    uint4* out4 = (uint4*)g_Th + ((size_t)(b * HW) + p0) * 16;

    float sq = 0.0f;
#pragma unroll
    for (int c0 = 0; c0 < CH; c0 += 64) {
        if (c0) __syncthreads();
#pragma unroll
        for (int i = 0; i < 8; i++) {
            int c = c0 + ty + 8 * i;
            float v = er[((size_t)(b * CH + c)) * HW + p0 + tx];  // 128B coalesced
            tile[ty + 8 * i][tx] = v;
            sq += v * v;
        }
        __syncthreads();
        __half2 h[4];
#pragma unroll
        for (int m = 0; m < 4; m++)
            h[m] = __floats2half2_rn(tile[8 * quad + 2 * m][px],
                                     tile[8 * quad + 2 * m + 1][px]);
        out4[(size_t)px * 16 + c0 / 8 + quad] = *(uint4*)h;   // STG.128
    }
    red[ty][tx] = sq;
    __syncthreads();
    if (ty == 0) {   // warp 0: inv-norm + prep for this block's 32 pixels
        float s = 0.0f;
#pragma unroll
        for (int k = 0; k < 8; k++) s += red[k][tx];
        int rem = p0 + tx;
        int p   = b * HW + rem;
        g_inv[p] = 1.0f / fmaxf(sqrtf(s), 1e-8f);

        int y = rem / WW;
        int x = rem - y * WW;
        int s1r = seg[((size_t)(b * 2 + 1)) * HW + rem];
        int gt  = gtb[p];            if (gt == 255) gt = 0;
        int s1  = s1r;               if (s1 == 255) s1 = 0;
        bool bnd = (gt * s1) > 0;
        bool inter = (y >= 2) && (y <= HH - 3) && (x >= 2) && (x <= WW - 3);
        bool sel = bnd && inter;
        g_cls[p] = (unsigned char)s1r;

        unsigned selm = __ballot_sync(0xffffffffu, sel);
        unsigned bndm = __ballot_sync(0xffffffffu, bnd);
        int base = 0;
        if (tx == 0 && selm) {
            base = atomicAdd(&g_nsel, __popc(selm));
            atomicAdd(&g_cnt[b], __popc(selm));
        }
        if (tx == 0 && bndm) atomicOr(&g_bnd[b], 1);
        base = __shfl_sync(0xffffffffu, base, 0);
        if (sel) g_list[base + __popc(selm & ((1u << tx) - 1u))] = p;
    }
}

// ---------------------------------------------------------------------------
// 2. main: 4 pixels/warp, 8 lanes/pixel (16 ch/lane, FULL 128B-line wavefronts);
//    3 neighbor groups of 8 (dots[8] live); packed HFMA2; fused finalize+reset
__global__ void __launch_bounds__(256, 5)
ctx_kernel(float* __restrict__ out) {
    __shared__ float sacc[BATCH];
    int tid  = threadIdx.x;
    int nsel = g_nsel;

    if (blockIdx.x * 32 < nsel) {
        if (tid < BATCH) sacc[tid] = 0.0f;
        __syncthreads();

        int warp = blockIdx.x * 8 + (tid >> 5);
        int lane = tid & 31;
        int grp  = lane >> 3;               // pixel within warp (0..3)
        int sub  = lane & 7;                // lane within pixel (0..7)

        int idx = warp * 4 + grp;
        bool active = idx < nsel;
        int p = active ? g_list[idx] : (2 * WW + 2);

        // center: 16 channels per lane = 2 uint4 at line-aligned offsets
        const uint4* base4 = (const uint4*)(g_Th + (size_t)p * CH);
        __half2 chv[8];
        {
            uint4 ua = base4[sub];
            uint4 ub = base4[sub + 8];
            *(uint4*)&chv[0] = ua;
            *(uint4*)&chv[4] = ub;
        }
        float invc = g_inv[p];
        unsigned char cp = g_cls[p];

        float acc = 0.0f;
#pragma unroll
        for (int g = 0; g < 3; g++) {
            float dots[8];
#pragma unroll
            for (int jj = 0; jj < 8; jj++) {
                int q = p + c_off[g * 8 + jj];
                const uint4* nb4 = (const uint4*)(g_Th + (size_t)q * CH);
                uint4 na = nb4[sub];         // warp: 4 full 128B lines
                uint4 nb = nb4[sub + 8];     // warp: 4 full 128B lines
                const __half2* ha = (const __half2*)&na;
                const __half2* hb = (const __half2*)&nb;
                __half2 d = __hmul2(chv[0], ha[0]);
                d = __hfma2(chv[1], ha[1], d);
                d = __hfma2(chv[2], ha[2], d);
                d = __hfma2(chv[3], ha[3], d);
                d = __hfma2(chv[4], hb[0], d);
                d = __hfma2(chv[5], hb[1], d);
                d = __hfma2(chv[6], hb[2], d);
                d = __hfma2(chv[7], hb[3], d);
                float2 f2 = __half22float2(d);
                dots[jj] = f2.x + f2.y;
            }
            // 8 independent 3-stage butterflies over the 8-lane group
#pragma unroll
            for (int m = 1; m <= 4; m <<= 1) {
#pragma unroll
                for (int jj = 0; jj < 8; jj++)
                    dots[jj] += __shfl_xor_sync(0xffffffffu, dots[jj], m);
            }
            // epilogue: lane sub handles neighbor g*8+sub
            if (active) {
                int j = g * 8 + sub;
                int q = p + c_off[j];
                float cosv = dots[sub] * invc * g_inv[q];
                float lab  = (g_cls[q] == cp) ? 1.0f : 0.0f;
                float e = cosv - lab;
                acc += e * e;
            }
        }
#pragma unroll
        for (int m = 1; m <= 4; m <<= 1)
            acc += __shfl_xor_sync(0xffffffffu, acc, m);
        if (sub == 0 && active) atomicAdd(&sacc[p / HW], acc);

        __syncthreads();
        if (tid < BATCH) {
            float v = sacc[tid];
            if (v != 0.0f) atomicAdd(&g_acc[tid], v);
        }
        __syncthreads();
    }

    // fused finalize + state reset for the next graph replay
    if (tid == 0) {
        __threadfence();
        int done = atomicAdd(&g_done, 1);
        if (done == (int)gridDim.x - 1) {
            float tot = 0.0f, nv = 0.0f;
            for (int b = 0; b < BATCH; b++) {
                float lb = g_acc[b] / fmaxf((float)g_cnt[b], 1.0f) / 24.0f;
                if (g_bnd[b]) { tot += lb; nv += 1.0f; }
            }
            tot = tot / fmaxf(nv, 1.0f);
            if (isnan(tot)) tot = 0.0f;
            out[0] = tot;
            // reset globals so the next replay starts clean
            for (int b = 0; b < BATCH; b++) {
                g_acc[b] = 0.0f; g_cnt[b] = 0; g_bnd[b] = 0;
            }
            g_nsel = 0;
            __threadfence();
            g_done = 0;
        }
    }
}

// ---------------------------------------------------------------------------
extern "C" void kernel_launch(void* const* d_in, const int* in_sizes, int n_in,
                              void* d_out, int out_size) {
    const float* er  = (const float*)d_in[0];
    const int*   seg = (const int*)d_in[1];
    const int*   gtb = (const int*)d_in[2];
    float*       out = (float*)d_out;

    transpose_kernel<<<dim3(HW / 32, BATCH), dim3(32, 8)>>>(er, seg, gtb);
    ctx_kernel<<<CTX_BLOCKS, 256>>>(out);
}

// round 13
// speedup vs baseline: 1.2479x; 1.0683x over previous
#include <cuda_runtime.h>
#include <cuda_fp16.h>
#include <math.h>

#define BATCH 4
#define CH    128
#define HH    384
#define WW    384
#define HW    (HH*WW)          // 147456
#define NPIX  (BATCH*HW)

#define MAXSEL ((HH-4)*(WW-4)*BATCH)      // 577600
#define CTX_BLOCKS ((MAXSEL + 31) / 32)   // 8 warps/block, 4 px/warp

// Scratch (allocation-free: __device__ globals; zero-initialized at load,
// re-zeroed by the finalize block at the end of every run)
__device__ unsigned char g_T8[(size_t)NPIX * CH]; // [B,H,W,C] e4m3 features (75 MB)
__device__ float         g_inv[NPIX];
__device__ unsigned char g_cls[NPIX];
__device__ int           g_list[NPIX];
__device__ int           g_nsel;
__device__ float         g_acc[BATCH];
__device__ int           g_cnt[BATCH];
__device__ int           g_bnd[BATCH];
__device__ int           g_done;

__constant__ int c_off[24] = {
    -770,-769,-768,-767,-766,
    -386,-385,-384,-383,-382,
      -2,  -1,   1,   2,
     382, 383, 384, 385, 386,
     766, 767, 768, 769, 770 };

// ---- fp8 conversion helpers -----------------------------------------------
__device__ __forceinline__ unsigned short f32x2_to_e4m3x2(float lo, float hi) {
    unsigned short r;   // first PTX source -> high byte
    asm("cvt.rn.satfinite.e4m3x2.f32 %0, %1, %2;" : "=h"(r) : "f"(hi), "f"(lo));
    return r;
}
__device__ __forceinline__ __half2 e4m3x2_to_h2(unsigned short s) {
    unsigned r;
    asm("cvt.rn.f16x2.e4m3x2 %0, %1;" : "=r"(r) : "h"(s));
    return *reinterpret_cast<__half2*>(&r);
}

// ---------------------------------------------------------------------------
// 1. transpose [B,C,H,W] -> [B,H,W,C] e4m3, fused fp32 inv-norm + prep
//    (mask/compaction/class). Block: 32 pixels x 128 channels, 2 chunks of 64.
__global__ void transpose_kernel(const float* __restrict__ er,
                                 const int* __restrict__ seg,
                                 const int* __restrict__ gtb) {
    __shared__ float tile[64][33];
    __shared__ float red[8][32];
    int tx = threadIdx.x, ty = threadIdx.y;
    int t  = ty * 32 + tx;
    int p0 = blockIdx.x * 32;
    int b  = blockIdx.y;
    int px  = t >> 3;                 // output pixel 0..31
    int oct = t & 7;                  // 8-byte group within 64-ch chunk

    uint2* out2 = (uint2*)g_T8 + ((size_t)(b * HW) + p0) * 16;

    float sq = 0.0f;
#pragma unroll
    for (int c0 = 0; c0 < CH; c0 += 64) {
        if (c0) __syncthreads();
#pragma unroll
        for (int i = 0; i < 8; i++) {
            int c = c0 + ty + 8 * i;
            float v = er[((size_t)(b * CH + c)) * HW + p0 + tx];  // 128B coalesced
            tile[ty + 8 * i][tx] = v;
            sq += v * v;
        }
        __syncthreads();
        // thread converts channels [c0+8*oct, +8) of pixel px -> 8 fp8 -> STG.64
        unsigned short s[4];
#pragma unroll
        for (int m = 0; m < 4; m++)
            s[m] = f32x2_to_e4m3x2(tile[8 * oct + 2 * m][px],
                                   tile[8 * oct + 2 * m + 1][px]);
        uint2 v;
        v.x = (unsigned)s[0] | ((unsigned)s[1] << 16);
        v.y = (unsigned)s[2] | ((unsigned)s[3] << 16);
        out2[(size_t)px * 16 + c0 / 8 + oct] = v;
    }
    red[ty][tx] = sq;
    __syncthreads();
    if (ty == 0) {   // warp 0: inv-norm + prep for this block's 32 pixels
        float s = 0.0f;
#pragma unroll
        for (int k = 0; k < 8; k++) s += red[k][tx];
        int rem = p0 + tx;
        int p   = b * HW + rem;
        g_inv[p] = 1.0f / fmaxf(sqrtf(s), 1e-8f);

        int y = rem / WW;
        int x = rem - y * WW;
        int s1r = seg[((size_t)(b * 2 + 1)) * HW + rem];
        int gt  = gtb[p];            if (gt == 255) gt = 0;
        int s1  = s1r;               if (s1 == 255) s1 = 0;
        bool bnd = (gt * s1) > 0;
        bool inter = (y >= 2) && (y <= HH - 3) && (x >= 2) && (x <= WW - 3);
        bool sel = bnd && inter;
        g_cls[p] = (unsigned char)s1r;

        unsigned selm = __ballot_sync(0xffffffffu, sel);
        unsigned bndm = __ballot_sync(0xffffffffu, bnd);
        int base = 0;
        if (tx == 0 && selm) {
            base = atomicAdd(&g_nsel, __popc(selm));
            atomicAdd(&g_cnt[b], __popc(selm));
        }
        if (tx == 0 && bndm) atomicOr(&g_bnd[b], 1);
        base = __shfl_sync(0xffffffffu, base, 0);
        if (sel) g_list[base + __popc(selm & ((1u << tx) - 1u))] = p;
    }
}

// ---------------------------------------------------------------------------
// 2. main: 4 pixels/warp, 8 lanes/pixel; ONE LDG.128 per neighbor covers the
//    full 128-fp8 pixel; cvt->HFMA2 chains; 3 neighbor groups; fused finalize
__global__ void __launch_bounds__(256, 5)
ctx_kernel(float* __restrict__ out) {
    __shared__ float sacc[BATCH];
    int tid  = threadIdx.x;
    int nsel = g_nsel;

    if (blockIdx.x * 32 < nsel) {
        if (tid < BATCH) sacc[tid] = 0.0f;
        __syncthreads();

        int warp = blockIdx.x * 8 + (tid >> 5);
        int lane = tid & 31;
        int grp  = lane >> 3;               // pixel within warp (0..3)
        int sub  = lane & 7;                // lane within pixel (0..7)

        int idx = warp * 4 + grp;
        bool active = idx < nsel;
        int p = active ? g_list[idx] : (2 * WW + 2);

        // center: 16 channels (16 bytes) per lane -> 8 half2 (converted once)
        uint4 cv = ((const uint4*)(g_T8 + (size_t)p * CH))[sub];
        __half2 chv[8];
        {
            const unsigned short* cs = (const unsigned short*)&cv;
#pragma unroll
            for (int k = 0; k < 8; k++) chv[k] = e4m3x2_to_h2(cs[k]);
        }
        float invc = g_inv[p];
        unsigned char cp = g_cls[p];

        float acc = 0.0f;
#pragma unroll
        for (int g = 0; g < 3; g++) {
            float dots[8];
#pragma unroll
            for (int jj = 0; jj < 8; jj++) {
                int q = p + c_off[g * 8 + jj];
                uint4 nv = ((const uint4*)(g_T8 + (size_t)q * CH))[sub]; // full line/warp
                const unsigned short* ns = (const unsigned short*)&nv;
                __half2 d = __hmul2(chv[0], e4m3x2_to_h2(ns[0]));
                d = __hfma2(chv[1], e4m3x2_to_h2(ns[1]), d);
                d = __hfma2(chv[2], e4m3x2_to_h2(ns[2]), d);
                d = __hfma2(chv[3], e4m3x2_to_h2(ns[3]), d);
                d = __hfma2(chv[4], e4m3x2_to_h2(ns[4]), d);
                d = __hfma2(chv[5], e4m3x2_to_h2(ns[5]), d);
                d = __hfma2(chv[6], e4m3x2_to_h2(ns[6]), d);
                d = __hfma2(chv[7], e4m3x2_to_h2(ns[7]), d);
                float2 f2 = __half22float2(d);
                dots[jj] = f2.x + f2.y;
            }
            // 8 independent 3-stage butterflies over the 8-lane group
#pragma unroll
            for (int m = 1; m <= 4; m <<= 1) {
#pragma unroll
                for (int jj = 0; jj < 8; jj++)
                    dots[jj] += __shfl_xor_sync(0xffffffffu, dots[jj], m);
            }
            // epilogue: lane sub handles neighbor g*8+sub
            if (active) {
                int j = g * 8 + sub;
                int q = p + c_off[j];
                float cosv = dots[sub] * invc * g_inv[q];
                float lab  = (g_cls[q] == cp) ? 1.0f : 0.0f;
                float e = cosv - lab;
                acc += e * e;
            }
        }
#pragma unroll
        for (int m = 1; m <= 4; m <<= 1)
            acc += __shfl_xor_sync(0xffffffffu, acc, m);
        if (sub == 0 && active) atomicAdd(&sacc[p / HW], acc);

        __syncthreads();
        if (tid < BATCH) {
            float v = sacc[tid];
            if (v != 0.0f) atomicAdd(&g_acc[tid], v);
        }
        __syncthreads();
    }

    // fused finalize + state reset for the next graph replay
    if (tid == 0) {
        __threadfence();
        int done = atomicAdd(&g_done, 1);
        if (done == (int)gridDim.x - 1) {
            float tot = 0.0f, nv = 0.0f;
            for (int b = 0; b < BATCH; b++) {
                float lb = g_acc[b] / fmaxf((float)g_cnt[b], 1.0f) / 24.0f;
                if (g_bnd[b]) { tot += lb; nv += 1.0f; }
            }
            tot = tot / fmaxf(nv, 1.0f);
            if (isnan(tot)) tot = 0.0f;
            out[0] = tot;
            for (int b = 0; b < BATCH; b++) {
                g_acc[b] = 0.0f; g_cnt[b] = 0; g_bnd[b] = 0;
            }
            g_nsel = 0;
            __threadfence();
            g_done = 0;
        }
    }
}

// ---------------------------------------------------------------------------
extern "C" void kernel_launch(void* const* d_in, const int* in_sizes, int n_in,
                              void* d_out, int out_size) {
    const float* er  = (const float*)d_in[0];
    const int*   seg = (const int*)d_in[1];
    const int*   gtb = (const int*)d_in[2];
    float*       out = (float*)d_out;

    transpose_kernel<<<dim3(HW / 32, BATCH), dim3(32, 8)>>>(er, seg, gtb);
    ctx_kernel<<<CTX_BLOCKS, 256>>>(out);
}

// round 14
// speedup vs baseline: 1.2891x; 1.0330x over previous
#include <cuda_runtime.h>
#include <cuda_fp16.h>
#include <math.h>

#define BATCH 4
#define CH    128
#define HH    384
#define WW    384
#define HW    (HH*WW)          // 147456
#define NPIX  (BATCH*HW)

#define MAXSEL ((HH-4)*(WW-4)*BATCH)      // 577600
#define CTX_BLOCKS ((MAXSEL + 31) / 32)   // 8 warps/block, 4 px/warp

// Scratch (allocation-free: __device__ globals; zero-initialized at load,
// re-zeroed by the finalize block at the end of every run)
__device__ unsigned char g_T8[(size_t)NPIX * CH]; // [B,H,W,C] e4m3 features (75 MB)
__device__ float         g_inv[NPIX];
__device__ unsigned char g_cls[NPIX];
__device__ int           g_list[NPIX];
__device__ int           g_nsel;
__device__ float         g_acc[BATCH];
__device__ int           g_cnt[BATCH];
__device__ int           g_bnd[BATCH];
__device__ int           g_done;

// ---- fp8 conversion helpers -----------------------------------------------
__device__ __forceinline__ unsigned short f32x2_to_e4m3x2(float lo, float hi) {
    unsigned short r;   // first PTX source -> high byte
    asm("cvt.rn.satfinite.e4m3x2.f32 %0, %1, %2;" : "=h"(r) : "f"(hi), "f"(lo));
    return r;
}
__device__ __forceinline__ __half2 e4m3x2_to_h2(unsigned short s) {
    unsigned r;
    asm("cvt.rn.f16x2.e4m3x2 %0, %1;" : "=r"(r) : "h"(s));
    return *reinterpret_cast<__half2*>(&r);
}

// packed-merge step: combine two distributed values a,b over lane pairs (xor m).
// After the step, lanes with sel=0 carry value-a partials, sel=1 carry value-b.
__device__ __forceinline__ float bmerge(float a, float b, bool sel, int m) {
    float keep = sel ? b : a;
    float send = sel ? a : b;
    return keep + __shfl_xor_sync(0xffffffffu, send, m);
}

// ---------------------------------------------------------------------------
// 1. transpose [B,C,H,W] -> [B,H,W,C] e4m3, fused fp32 inv-norm + prep
//    (mask/compaction/class). Block: 32 pixels x 128 channels, 2 chunks of 64.
__global__ void transpose_kernel(const float* __restrict__ er,
                                 const int* __restrict__ seg,
                                 const int* __restrict__ gtb) {
    __shared__ float tile[64][33];
    __shared__ float red[8][32];
    int tx = threadIdx.x, ty = threadIdx.y;
    int t  = ty * 32 + tx;
    int p0 = blockIdx.x * 32;
    int b  = blockIdx.y;
    int px  = t >> 3;                 // output pixel 0..31
    int oct = t & 7;                  // 8-byte group within 64-ch chunk

    uint2* out2 = (uint2*)g_T8 + ((size_t)(b * HW) + p0) * 16;

    float sq = 0.0f;
#pragma unroll
    for (int c0 = 0; c0 < CH; c0 += 64) {
        if (c0) __syncthreads();
#pragma unroll
        for (int i = 0; i < 8; i++) {
            int c = c0 + ty + 8 * i;
            float v = er[((size_t)(b * CH + c)) * HW + p0 + tx];  // 128B coalesced
            tile[ty + 8 * i][tx] = v;
            sq += v * v;
        }
        __syncthreads();
        unsigned short s[4];
#pragma unroll
        for (int m = 0; m < 4; m++)
            s[m] = f32x2_to_e4m3x2(tile[8 * oct + 2 * m][px],
                                   tile[8 * oct + 2 * m + 1][px]);
        uint2 v;
        v.x = (unsigned)s[0] | ((unsigned)s[1] << 16);
        v.y = (unsigned)s[2] | ((unsigned)s[3] << 16);
        out2[(size_t)px * 16 + c0 / 8 + oct] = v;
    }
    red[ty][tx] = sq;
    __syncthreads();
    if (ty == 0) {   // warp 0: inv-norm + prep for this block's 32 pixels
        float s = 0.0f;
#pragma unroll
        for (int k = 0; k < 8; k++) s += red[k][tx];
        int rem = p0 + tx;
        int p   = b * HW + rem;
        g_inv[p] = 1.0f / fmaxf(sqrtf(s), 1e-8f);

        int y = rem / WW;
        int x = rem - y * WW;
        int s1r = seg[((size_t)(b * 2 + 1)) * HW + rem];
        int gt  = gtb[p];            if (gt == 255) gt = 0;
        int s1  = s1r;               if (s1 == 255) s1 = 0;
        bool bnd = (gt * s1) > 0;
        bool inter = (y >= 2) && (y <= HH - 3) && (x >= 2) && (x <= WW - 3);
        bool sel = bnd && inter;
        g_cls[p] = (unsigned char)s1r;

        unsigned selm = __ballot_sync(0xffffffffu, sel);
        unsigned bndm = __ballot_sync(0xffffffffu, bnd);
        int base = 0;
        if (tx == 0 && selm) {
            base = atomicAdd(&g_nsel, __popc(selm));
            atomicAdd(&g_cnt[b], __popc(selm));
        }
        if (tx == 0 && bndm) atomicOr(&g_bnd[b], 1);
        base = __shfl_sync(0xffffffffu, base, 0);
        if (sel) g_list[base + __popc(selm & ((1u << tx) - 1u))] = p;
    }
}

// ---------------------------------------------------------------------------
// 2. main: 4 pixels/warp, 8 lanes/pixel; one LDG.128 per neighbor covers the
//    full 128-fp8 pixel; cvt->HFMA2; packed-merge butterflies; constexpr
//    immediate offsets; fused finalize
__global__ void __launch_bounds__(256, 5)
ctx_kernel(float* __restrict__ out) {
    constexpr int OFF[24] = {
        -770,-769,-768,-767,-766,
        -386,-385,-384,-383,-382,
          -2,  -1,   1,   2,
         382, 383, 384, 385, 386,
         766, 767, 768, 769, 770 };

    __shared__ float sacc[BATCH];
    int tid  = threadIdx.x;
    int nsel = g_nsel;

    if (blockIdx.x * 32 < nsel) {
        if (tid < BATCH) sacc[tid] = 0.0f;
        __syncthreads();

        int warp = blockIdx.x * 8 + (tid >> 5);
        int lane = tid & 31;
        int grp  = lane >> 3;               // pixel within warp (0..3)
        int sub  = lane & 7;                // lane within pixel (0..7)
        bool b0 = sub & 1, b1 = sub & 2, b2 = sub & 4;

        int idx = warp * 4 + grp;
        bool active = idx < nsel;
        int p = active ? g_list[idx] : (2 * WW + 2);

        const unsigned char* pbase = g_T8 + (size_t)p * CH + sub * 16;
        uint4 cv = *(const uint4*)pbase;
        __half2 chv[8];
        {
            const unsigned short* cs = (const unsigned short*)&cv;
#pragma unroll
            for (int k = 0; k < 8; k++) chv[k] = e4m3x2_to_h2(cs[k]);
        }
        float invc = g_inv[p];
        unsigned char cp = g_cls[p];

        float acc = 0.0f;
#pragma unroll
        for (int g = 0; g < 3; g++) {
            float dots[8];
#pragma unroll
            for (int jj = 0; jj < 8; jj++) {
                // constexpr offset -> immediate in the LDG
                uint4 nv = *(const uint4*)(pbase + OFF[g * 8 + jj] * CH);
                const unsigned short* ns = (const unsigned short*)&nv;
                __half2 d = __hmul2(chv[0], e4m3x2_to_h2(ns[0]));
                d = __hfma2(chv[1], e4m3x2_to_h2(ns[1]), d);
                d = __hfma2(chv[2], e4m3x2_to_h2(ns[2]), d);
                d = __hfma2(chv[3], e4m3x2_to_h2(ns[3]), d);
                d = __hfma2(chv[4], e4m3x2_to_h2(ns[4]), d);
                d = __hfma2(chv[5], e4m3x2_to_h2(ns[5]), d);
                d = __hfma2(chv[6], e4m3x2_to_h2(ns[6]), d);
                d = __hfma2(chv[7], e4m3x2_to_h2(ns[7]), d);
                float2 f2 = __half22float2(d);
                dots[jj] = f2.x + f2.y;
            }
            // packed-merge reduction: lane sub ends with full sum of dots[sub]
            float t0 = bmerge(dots[0], dots[1], b0, 1);
            float t1 = bmerge(dots[2], dots[3], b0, 1);
            float t2 = bmerge(dots[4], dots[5], b0, 1);
            float t3 = bmerge(dots[6], dots[7], b0, 1);
            float u0 = bmerge(t0, t1, b1, 2);
            float u1 = bmerge(t2, t3, b1, 2);
            float w  = bmerge(u0, u1, b2, 4);

            // epilogue: lane sub handles neighbor g*8+sub
            if (active) {
                int j = g * 8 + sub;
                int q = p + OFF[j];
                float cosv = w * invc * g_inv[q];
                float lab  = (g_cls[q] == cp) ? 1.0f : 0.0f;
                float e = cosv - lab;
                acc += e * e;
            }
        }
#pragma unroll
        for (int m = 1; m <= 4; m <<= 1)
            acc += __shfl_xor_sync(0xffffffffu, acc, m);
        if (sub == 0 && active) atomicAdd(&sacc[p / HW], acc);

        __syncthreads();
        if (tid < BATCH) {
            float v = sacc[tid];
            if (v != 0.0f) atomicAdd(&g_acc[tid], v);
        }
        __syncthreads();
    }

    // fused finalize + state reset for the next graph replay
    if (tid == 0) {
        __threadfence();
        int done = atomicAdd(&g_done, 1);
        if (done == (int)gridDim.x - 1) {
            float tot = 0.0f, nv = 0.0f;
            for (int b = 0; b < BATCH; b++) {
                float lb = g_acc[b] / fmaxf((float)g_cnt[b], 1.0f) / 24.0f;
                if (g_bnd[b]) { tot += lb; nv += 1.0f; }
            }
            tot = tot / fmaxf(nv, 1.0f);
            if (isnan(tot)) tot = 0.0f;
            out[0] = tot;
            for (int b = 0; b < BATCH; b++) {
                g_acc[b] = 0.0f; g_cnt[b] = 0; g_bnd[b] = 0;
            }
            g_nsel = 0;
            __threadfence();
            g_done = 0;
        }
    }
}

// ---------------------------------------------------------------------------
extern "C" void kernel_launch(void* const* d_in, const int* in_sizes, int n_in,
                              void* d_out, int out_size) {
    const float* er  = (const float*)d_in[0];
    const int*   seg = (const int*)d_in[1];
    const int*   gtb = (const int*)d_in[2];
    float*       out = (float*)d_out;

    transpose_kernel<<<dim3(HW / 32, BATCH), dim3(32, 8)>>>(er, seg, gtb);
    ctx_kernel<<<CTX_BLOCKS, 256>>>(out);
}

// round 15
// speedup vs baseline: 1.4509x; 1.1255x over previous
#include <cuda_runtime.h>
#include <cuda_fp16.h>
#include <math.h>

#define BATCH 4
#define CH    128
#define HH    384
#define WW    384
#define HW    (HH*WW)          // 147456
#define NPIX  (BATCH*HW)

#define MAXSEL ((HH-4)*(WW-4)*BATCH)      // 577600
#define CTX_BLOCKS ((MAXSEL + 31) / 32)   // 8 warps/block, 4 px/warp

// Scratch (allocation-free: __device__ globals; zero-initialized at load,
// re-zeroed by the finalize block at the end of every run)
__device__ unsigned char g_T8[(size_t)NPIX * CH]; // [B,H,W,C] e4m3 features (75 MB)
__device__ float         g_inv[NPIX];
__device__ unsigned char g_cls[NPIX];
__device__ int           g_list[NPIX];
__device__ int           g_nsel;
__device__ float         g_acc[BATCH];
__device__ int           g_cnt[BATCH];
__device__ int           g_bnd[BATCH];
__device__ int           g_done;

// ---- fp8 conversion helpers -----------------------------------------------
__device__ __forceinline__ unsigned short f32x2_to_e4m3x2(float lo, float hi) {
    unsigned short r;   // first PTX source -> high byte
    asm("cvt.rn.satfinite.e4m3x2.f32 %0, %1, %2;" : "=h"(r) : "f"(hi), "f"(lo));
    return r;
}
__device__ __forceinline__ __half2 e4m3x2_to_h2(unsigned short s) {
    unsigned r;
    asm("cvt.rn.f16x2.e4m3x2 %0, %1;" : "=r"(r) : "h"(s));
    return *reinterpret_cast<__half2*>(&r);
}

// packed-merge step: combine two distributed values a,b over lane pairs (xor m).
__device__ __forceinline__ float bmerge(float a, float b, bool sel, int m) {
    float keep = sel ? b : a;
    float send = sel ? a : b;
    return keep + __shfl_xor_sync(0xffffffffu, send, m);
}

// ---------------------------------------------------------------------------
// 1. transpose [B,C,H,W] -> [B,H,W,C] e4m3, single-phase smem tile (all 128
//    channels resident -> 16 batched LDGs, ONE sync), fused inv-norm + prep.
__global__ void transpose_kernel(const float* __restrict__ er,
                                 const int* __restrict__ seg,
                                 const int* __restrict__ gtb) {
    __shared__ float tile[128][33];   // 16.9 KB: whole 32px x 128ch block
    __shared__ float red[8][32];
    int tx = threadIdx.x, ty = threadIdx.y;
    int t  = ty * 32 + tx;
    int p0 = blockIdx.x * 32;
    int b  = blockIdx.y;
    int px  = t >> 3;                 // output pixel 0..31
    int oct = t & 7;                  // 8-byte group within 64-ch chunk

    uint2* out2 = (uint2*)g_T8 + ((size_t)(b * HW) + p0) * 16;

    float sq = 0.0f;
#pragma unroll
    for (int i = 0; i < 16; i++) {    // 16 independent LDGs up-front (MLP)
        int c = ty + 8 * i;
        float v = er[((size_t)(b * CH + c)) * HW + p0 + tx];  // 128B coalesced
        tile[c][tx] = v;
        sq += v * v;
    }
    red[ty][tx] = sq;
    __syncthreads();

#pragma unroll
    for (int h = 0; h < 2; h++) {     // both 64-channel chunks from one tile
        unsigned short s[4];
#pragma unroll
        for (int m = 0; m < 4; m++)
            s[m] = f32x2_to_e4m3x2(tile[64 * h + 8 * oct + 2 * m][px],
                                   tile[64 * h + 8 * oct + 2 * m + 1][px]);
        uint2 v;
        v.x = (unsigned)s[0] | ((unsigned)s[1] << 16);
        v.y = (unsigned)s[2] | ((unsigned)s[3] << 16);
        out2[(size_t)px * 16 + 8 * h + oct] = v;
    }

    if (ty == 0) {   // warp 0: inv-norm + prep for this block's 32 pixels
        float s = 0.0f;
#pragma unroll
        for (int k = 0; k < 8; k++) s += red[k][tx];
        int rem = p0 + tx;
        int p   = b * HW + rem;
        g_inv[p] = 1.0f / fmaxf(sqrtf(s), 1e-8f);

        int y = rem / WW;
        int x = rem - y * WW;
        int s1r = seg[((size_t)(b * 2 + 1)) * HW + rem];
        int gt  = gtb[p];            if (gt == 255) gt = 0;
        int s1  = s1r;               if (s1 == 255) s1 = 0;
        bool bnd = (gt * s1) > 0;
        bool inter = (y >= 2) && (y <= HH - 3) && (x >= 2) && (x <= WW - 3);
        bool sel = bnd && inter;
        g_cls[p] = (unsigned char)s1r;

        unsigned selm = __ballot_sync(0xffffffffu, sel);
        unsigned bndm = __ballot_sync(0xffffffffu, bnd);
        int base = 0;
        if (tx == 0 && selm) {
            base = atomicAdd(&g_nsel, __popc(selm));
            atomicAdd(&g_cnt[b], __popc(selm));
        }
        if (tx == 0 && bndm) atomicOr(&g_bnd[b], 1);
        base = __shfl_sync(0xffffffffu, base, 0);
        if (sel) g_list[base + __popc(selm & ((1u << tx) - 1u))] = p;
    }
}

// ---------------------------------------------------------------------------
// 2. main: 4 pixels/warp, 8 lanes/pixel; one LDG.128 per neighbor; cvt->HFMA2;
//    packed-merge butterflies; 6 blocks/SM for latency hiding; fused finalize
__global__ void __launch_bounds__(256, 6)
ctx_kernel(float* __restrict__ out) {
    constexpr int OFF[24] = {
        -770,-769,-768,-767,-766,
        -386,-385,-384,-383,-382,
          -2,  -1,   1,   2,
         382, 383, 384, 385, 386,
         766, 767, 768, 769, 770 };

    __shared__ float sacc[BATCH];
    int tid  = threadIdx.x;
    int nsel = g_nsel;

    if (blockIdx.x * 32 < nsel) {
        if (tid < BATCH) sacc[tid] = 0.0f;
        __syncthreads();

        int warp = blockIdx.x * 8 + (tid >> 5);
        int lane = tid & 31;
        int grp  = lane >> 3;               // pixel within warp (0..3)
        int sub  = lane & 7;                // lane within pixel (0..7)
        bool b0 = sub & 1, b1 = sub & 2, b2 = sub & 4;

        int idx = warp * 4 + grp;
        bool active = idx < nsel;
        int p = active ? g_list[idx] : (2 * WW + 2);

        const unsigned char* pbase = g_T8 + (size_t)p * CH + sub * 16;
        uint4 cv = *(const uint4*)pbase;
        __half2 chv[8];
        {
            const unsigned short* cs = (const unsigned short*)&cv;
#pragma unroll
            for (int k = 0; k < 8; k++) chv[k] = e4m3x2_to_h2(cs[k]);
        }
        float invc = g_inv[p];
        unsigned char cp = g_cls[p];

        float acc = 0.0f;
#pragma unroll
        for (int g = 0; g < 3; g++) {
            float dots[8];
#pragma unroll
            for (int jj = 0; jj < 8; jj++) {
                uint4 nv = *(const uint4*)(pbase + OFF[g * 8 + jj] * CH);
                const unsigned short* ns = (const unsigned short*)&nv;
                __half2 d = __hmul2(chv[0], e4m3x2_to_h2(ns[0]));
                d = __hfma2(chv[1], e4m3x2_to_h2(ns[1]), d);
                d = __hfma2(chv[2], e4m3x2_to_h2(ns[2]), d);
                d = __hfma2(chv[3], e4m3x2_to_h2(ns[3]), d);
                d = __hfma2(chv[4], e4m3x2_to_h2(ns[4]), d);
                d = __hfma2(chv[5], e4m3x2_to_h2(ns[5]), d);
                d = __hfma2(chv[6], e4m3x2_to_h2(ns[6]), d);
                d = __hfma2(chv[7], e4m3x2_to_h2(ns[7]), d);
                float2 f2 = __half22float2(d);
                dots[jj] = f2.x + f2.y;
            }
            // packed-merge reduction: lane sub ends with full sum of dots[sub]
            float t0 = bmerge(dots[0], dots[1], b0, 1);
            float t1 = bmerge(dots[2], dots[3], b0, 1);
            float t2 = bmerge(dots[4], dots[5], b0, 1);
            float t3 = bmerge(dots[6], dots[7], b0, 1);
            float u0 = bmerge(t0, t1, b1, 2);
            float u1 = bmerge(t2, t3, b1, 2);
            float w  = bmerge(u0, u1, b2, 4);

            if (active) {
                int j = g * 8 + sub;
                int q = p + OFF[j];
                float cosv = w * invc * g_inv[q];
                float lab  = (g_cls[q] == cp) ? 1.0f : 0.0f;
                float e = cosv - lab;
                acc += e * e;
            }
        }
#pragma unroll
        for (int m = 1; m <= 4; m <<= 1)
            acc += __shfl_xor_sync(0xffffffffu, acc, m);
        if (sub == 0 && active) atomicAdd(&sacc[p / HW], acc);

        __syncthreads();
        if (tid < BATCH) {
            float v = sacc[tid];
            if (v != 0.0f) atomicAdd(&g_acc[tid], v);
        }
        __syncthreads();
    }

    // fused finalize + state reset for the next graph replay
    if (tid == 0) {
        __threadfence();
        int done = atomicAdd(&g_done, 1);
        if (done == (int)gridDim.x - 1) {
            float tot = 0.0f, nv = 0.0f;
            for (int b = 0; b < BATCH; b++) {
                float lb = g_acc[b] / fmaxf((float)g_cnt[b], 1.0f) / 24.0f;
                if (g_bnd[b]) { tot += lb; nv += 1.0f; }
            }
            tot = tot / fmaxf(nv, 1.0f);
            if (isnan(tot)) tot = 0.0f;
            out[0] = tot;
            for (int b = 0; b < BATCH; b++) {
                g_acc[b] = 0.0f; g_cnt[b] = 0; g_bnd[b] = 0;
            }
            g_nsel = 0;
            __threadfence();
            g_done = 0;
        }
    }
}

// ---------------------------------------------------------------------------
extern "C" void kernel_launch(void* const* d_in, const int* in_sizes, int n_in,
                              void* d_out, int out_size) {
    const float* er  = (const float*)d_in[0];
    const int*   seg = (const int*)d_in[1];
    const int*   gtb = (const int*)d_in[2];
    float*       out = (float*)d_out;

    transpose_kernel<<<dim3(HW / 32, BATCH), dim3(32, 8)>>>(er, seg, gtb);
    ctx_kernel<<<CTX_BLOCKS, 256>>>(out);
}